// round 14
// baseline (speedup 1.0000x reference)
#include <cuda_runtime.h>
#include <cuda_fp16.h>
#include <cstdint>
#include <cstddef>

#define B_ 256
#define T_ 512
#define H_ 256
#define I_ 64
#define CSZ 8
#define MR 16
#define NLOC 128
#define TCH 32

// ---------------- device scratch ----------------
__device__ float  g_h2last[B_ * H_];
__device__ __half g_whh0[CSZ * NLOC * 256];    // L0 recurrent weights, rank-sliced
__device__ __half g_w1cat[CSZ * NLOC * 512];   // L1 [Whh1|Wih1] rows, rank-sliced
__device__ __half g_wih0[CSZ * NLOC * 64];
__device__ float  g_bias0[CSZ * NLOC];
__device__ float  g_bias1[CSZ * NLOC];
// Precomputed L0 input-gate terms (bias folded): [cta(128), t(512), tid(256), 8]
__device__ float  g_xg0[(size_t)128 * 512 * 256 * 8];

// ---------------- helpers ----------------
__device__ __forceinline__ unsigned su32(const void* p) {
    unsigned a;
    asm("{ .reg .u64 t; cvta.to.shared.u64 t, %1; cvt.u32.u64 %0, t; }" : "=r"(a) : "l"(p));
    return a;
}
__device__ __forceinline__ float tanhap(float x) {
    float y;
    asm("tanh.approx.f32 %0, %1;" : "=f"(y) : "f"(x));
    return y;
}
__device__ __forceinline__ float sigm(float x) {
    return fmaf(tanhap(0.5f * x), 0.5f, 0.5f);
}
__device__ __forceinline__ void ldsm_x2(uint32_t& b0, uint32_t& b1, unsigned a) {
    asm volatile("ldmatrix.sync.aligned.m8n8.x2.shared.b16 {%0,%1}, [%2];"
                 : "=r"(b0), "=r"(b1) : "r"(a));
}
__device__ __forceinline__ void ldsm_x4(uint32_t* r, unsigned a) {
    asm volatile("ldmatrix.sync.aligned.m8n8.x4.shared.b16 {%0,%1,%2,%3}, [%4];"
                 : "=r"(r[0]), "=r"(r[1]), "=r"(r[2]), "=r"(r[3]) : "r"(a));
}
__device__ __forceinline__ void mma16816(float* acc, const uint32_t* a, uint32_t b0, uint32_t b1) {
    asm volatile(
        "mma.sync.aligned.m16n8k16.row.col.f32.f16.f16.f32 "
        "{%0,%1,%2,%3}, {%4,%5,%6,%7}, {%8,%9}, {%0,%1,%2,%3};"
        : "+f"(acc[0]), "+f"(acc[1]), "+f"(acc[2]), "+f"(acc[3])
        : "r"(a[0]), "r"(a[1]), "r"(a[2]), "r"(a[3]), "r"(b0), "r"(b1));
}

// ---------------- weight prep ----------------
// Local row l of rank r: gate g = l>>5, h-col = r*32 + (l&31), grow = g*256 + r*32 + (l&31).
__global__ void prep_kernel(const float* __restrict__ Wih0, const float* __restrict__ Whh0,
                            const float* __restrict__ bih0, const float* __restrict__ bhh0,
                            const float* __restrict__ Wih1, const float* __restrict__ Whh1,
                            const float* __restrict__ bih1, const float* __restrict__ bhh1) {
    int blk = blockIdx.x;
    int li = blk & 1023;
    int r = li >> 7, l = li & 127;
    int grow = (l >> 5) * H_ + r * 32 + (l & 31);
    if (blk < 1024) {
        for (int k = threadIdx.x; k < 256; k += blockDim.x)
            g_whh0[(r * NLOC + l) * 256 + k] = __float2half_rn(Whh0[grow * H_ + k]);
        for (int k = threadIdx.x; k < 64; k += blockDim.x)
            g_wih0[(r * NLOC + l) * 64 + k] = __float2half_rn(Wih0[grow * I_ + k]);
        if (threadIdx.x == 0) g_bias0[r * NLOC + l] = bih0[grow] + bhh0[grow];
    } else {
        for (int k = threadIdx.x; k < 512; k += blockDim.x) {
            float v = (k < 256) ? Whh1[grow * H_ + k] : Wih1[grow * H_ + (k - 256)];
            g_w1cat[(r * NLOC + l) * 512 + k] = __float2half_rn(v);
        }
        if (threadIdx.x == 0) g_bias1[r * NLOC + l] = bih1[grow] + bhh1[grow];
    }
}

// ---------------- time-parallel L0 input GEMM: xg0[cta,t,tid,0:8] ----------------
__global__ void __launch_bounds__(256) xg_gemm64(const float* __restrict__ xin) {
    constexpr int KT  = 4;
    constexpr int KPB = (64 + 8) * 2;   // 144

    extern __shared__ __align__(16) char smem[];
    char*  sW    = smem;
    char*  sB    = sW + NLOC * KPB;
    float* sG    = (float*)(sB + MR * KPB);
    float* sBias = sG + NLOC * 17;

    const int tid  = threadIdx.x;
    const int wid  = tid >> 5;
    const int lane = tid & 31;
    const int rank = blockIdx.x & 7;
    const int bm0  = (blockIdx.x >> 3) * MR;
    const int t0   = blockIdx.y * TCH;

    {
        const uint4* src = (const uint4*)(g_wih0 + (size_t)rank * NLOC * 64);
        for (int i = tid; i < NLOC * 8; i += 256) {
            int l = i >> 3, c = i & 7;
            *(uint4*)(sW + l * KPB + c * 16) = src[i];
        }
    }
    if (tid < NLOC) sBias[tid] = g_bias0[rank * NLOC + tid];
    __syncthreads();

    uint32_t wreg[KT][4];
    {
        unsigned rb = su32(sW) + (unsigned)(wid * 16 + (lane & 15)) * KPB + ((lane & 16) ? 16u : 0u);
#pragma unroll
        for (int kt = 0; kt < KT; kt++) ldsm_x4(wreg[kt], rb + kt * 32);
    }

    const unsigned sBu = su32(sB);
    const unsigned boffL = (unsigned)((lane & 7) * KPB) + ((lane & 8) ? 16u : 0u);
    const int gid = lane >> 2, ctid = lane & 3;
    const int m_act = tid >> 4, jj = tid & 15;
    const int mx = tid >> 4, cx = tid & 15;

    for (int tt = 0; tt < TCH; tt++) {
        const int t = t0 + tt;
        float4 v = *(const float4*)&xin[((size_t)(bm0 + mx) * T_ + t) * I_ + cx * 4];
        __half2* d = (__half2*)(sB + mx * KPB + cx * 8);
        d[0] = __floats2half2_rn(v.x, v.y);
        d[1] = __floats2half2_rn(v.z, v.w);
        __syncthreads();

        float accA[2][4] = {{0.f,0.f,0.f,0.f},{0.f,0.f,0.f,0.f}};
#pragma unroll
        for (int nt = 0; nt < 2; nt++) {
            unsigned bb = sBu + (unsigned)(nt * 8) * KPB + boffL;
#pragma unroll
            for (int kt = 0; kt < KT; kt++) {
                uint32_t b0, b1;
                ldsm_x2(b0, b1, bb + kt * 32);
                mma16816(accA[nt], wreg[kt], b0, b1);
            }
        }
#pragma unroll
        for (int nt = 0; nt < 2; nt++) {
            int col = nt * 8 + 2 * ctid;
            int row = wid * 16 + gid;
            sG[row * 17 + col]           = accA[nt][0];
            sG[row * 17 + col + 1]       = accA[nt][1];
            sG[(row + 8) * 17 + col]     = accA[nt][2];
            sG[(row + 8) * 17 + col + 1] = accA[nt][3];
        }
        __syncthreads();
        {
            int j0 = 2 * jj, j1 = j0 + 1;
            float4 oA, oB;
            oA.x = sG[(0  + j0) * 17 + m_act] + sBias[0  + j0];
            oA.y = sG[(0  + j1) * 17 + m_act] + sBias[0  + j1];
            oA.z = sG[(32 + j0) * 17 + m_act] + sBias[32 + j0];
            oA.w = sG[(32 + j1) * 17 + m_act] + sBias[32 + j1];
            oB.x = sG[(64 + j0) * 17 + m_act] + sBias[64 + j0];
            oB.y = sG[(64 + j1) * 17 + m_act] + sBias[64 + j1];
            oB.z = sG[(96 + j0) * 17 + m_act] + sBias[96 + j0];
            oB.w = sG[(96 + j1) * 17 + m_act] + sBias[96 + j1];
            size_t base = (((size_t)blockIdx.x * T_ + t) * 256 + tid) * 8;
            *(float4*)&g_xg0[base]     = oA;
            *(float4*)&g_xg0[base + 4] = oB;
        }
        __syncthreads();
    }
}

// ---------------- fused 2-layer wavefront loop ----------------
// Cluster of 8 CTAs = one batch group (16 rows). Rank r owns gate rows
// {g*256 + r*32 + j} and h-cols [r*32, r*32+32) for BOTH layers.
// Both weight sets in REGISTERS (wreg0: Whh0, wreg1: W1cat); one B-frag stream
// over hcat [h1|h0] feeds both GEMMs. DSMEM publish: paired u64 stores, 4 ranks
// per lane (even lane ranks 0-3, odd lane ranks 4-7), mapa precomputed.
__global__ void __launch_bounds__(256, 1) __cluster_dims__(CSZ, 1, 1)
lstm_fused() {
    constexpr int W1B   = 1040;            // W1cat / hcat row stride bytes (520 halves)
    constexpr int HCB   = MR * W1B;        // one hcat buffer = 16640 B
    constexpr int HC_OFF = NLOC * W1B;     // 133120
    constexpr int SG0_OFF = HC_OFF + 2 * HCB;          // 166400
    constexpr int SG1_OFF = SG0_OFF + NLOC * 17 * 4;   // 175104
    constexpr int SB1_OFF = SG1_OFF + NLOC * 17 * 4;   // 183808

    extern __shared__ __align__(16) char smem[];
    char*  sW1 = smem;                     // init-only staging
    char*  sHC = smem + HC_OFF;
    float* sG0 = (float*)(smem + SG0_OFF);
    float* sG1 = (float*)(smem + SG1_OFF);
    float* sB1 = (float*)(smem + SB1_OFF);

    const int tid  = threadIdx.x;
    const int wid  = tid >> 5;
    const int lane = tid & 31;
    unsigned rank;
    asm("mov.u32 %0, %%cluster_ctarank;" : "=r"(rank));
    const int bm0 = (blockIdx.x >> 3) * MR;

    const unsigned arow = (unsigned)(wid * 16 + (lane & 15)) * W1B + ((lane & 16) ? 16u : 0u);

    // ---- Phase A: stage Whh0 temporarily into sW1 region, grab wreg0 ----
    {
        const uint4* s0 = (const uint4*)(g_whh0 + (size_t)rank * NLOC * 256);
        for (int i = tid; i < NLOC * 32; i += 256) {
            int l = i >> 5, c = i & 31;
            *(uint4*)(sW1 + l * 528 + c * 16) = s0[i];
        }
    }
    __syncthreads();
    uint32_t wreg0[16][4];
    {
        unsigned rb = su32(sW1) + (unsigned)(wid * 16 + (lane & 15)) * 528 + ((lane & 16) ? 16u : 0u);
#pragma unroll
        for (int kt = 0; kt < 16; kt++) ldsm_x4(wreg0[kt], rb + kt * 32);
    }
    __syncthreads();

    // ---- Phase B: stage W1cat into sW1, grab wreg1, then sW1 is dead ----
    {
        const uint4* src = (const uint4*)(g_w1cat + (size_t)rank * NLOC * 512);
        for (int i = tid; i < NLOC * 64; i += 256) {
            int l = i >> 6, c = i & 63;
            *(uint4*)(sW1 + l * W1B + c * 16) = src[i];
        }
    }
    __syncthreads();
    uint32_t wreg1[32][4];
    {
        unsigned aW = su32(sW1) + arow;
#pragma unroll
        for (int kt = 0; kt < 32; kt++) ldsm_x4(wreg1[kt], aW + kt * 32);
    }
    __syncthreads();

    // ---- Phase C: zero hcat buffers, load bias ----
    for (int i = tid; i < 2 * HCB / 4; i += 256) ((unsigned*)sHC)[i] = 0u;
    if (tid < NLOC) sB1[tid] = g_bias1[rank * NLOC + tid];

    const unsigned sHCu = su32(sHC);
    const unsigned hoffL = (unsigned)((lane & 7) * W1B) + ((lane & 8) ? 16u : 0u);
    const int gid = lane >> 2, ctid = lane & 3;
    const int m_act = tid >> 4, jj = tid & 15;

    // ---- paired-u64 DSMEM publish setup ----
    // threads (tid even-jj, tid odd-jj) cover cols [colb, colb+3] of row m_act;
    // even lane stores ranks 0-3, odd lane ranks 4-7; bases precomputed via mapa
    // on the h1-slot address (h0 slot = +512, buffer toggle = +HCB, both post-mapa).
    const int colb = (jj >> 1) * 4;
    unsigned rb4[4];
    {
        const unsigned pairoff = sHCu + (unsigned)(m_act * W1B + (rank * 32 + colb) * 2);
        const int r0 = (lane & 1) * 4;
#pragma unroll
        for (int i = 0; i < 4; i++) {
            asm volatile("mapa.shared::cluster.u32 %0, %1, %2;"
                         : "=r"(rb4[i]) : "r"(pairoff), "r"(r0 + i));
        }
    }

    // xg0 stream
    const float4* xg4 = (const float4*)g_xg0;
    const size_t xbase = ((size_t)blockIdx.x * T_) * 512 + tid * 2;
    float4 xgA = xg4[xbase], xgB = xg4[xbase + 1];

    float c00 = 0.f, c01 = 0.f, c10 = 0.f, c11 = 0.f;

    __syncthreads();
    asm volatile("barrier.cluster.arrive.aligned;" ::: "memory");
    asm volatile("barrier.cluster.wait.aligned;" ::: "memory");

#pragma unroll 1
    for (int s = 0; s <= T_; s++) {
        const unsigned rb16 = (unsigned)((s & 1) * HCB);
        const unsigned wb16 = rb16 ^ (unsigned)HCB;
        const bool do0 = (s < T_);
        const bool do1 = (s >= 1);

        // prefetch xg[s+1]
        float4 pA, pB;
        if (do0) {
            int tn = (s + 1 < T_) ? s + 1 : s;
            pA = xg4[xbase + (size_t)tn * 512];
            pB = xg4[xbase + (size_t)tn * 512 + 1];
        }

        // ---- merged GEMMs: one B stream feeds both ----
#pragma unroll
        for (int nt = 0; nt < 2; nt++) {
            float a1e[4] = {0,0,0,0}, a1o[4] = {0,0,0,0};
            float a0e[4] = {0,0,0,0}, a0o[4] = {0,0,0,0};
            unsigned hb = sHCu + rb16 + hoffL + (unsigned)(nt * 8) * W1B;
#pragma unroll
            for (int kt = 0; kt < 32; kt++) {
                uint32_t b0, b1;
                ldsm_x2(b0, b1, hb + kt * 32);
                mma16816((kt & 1) ? a1o : a1e, wreg1[kt], b0, b1);
                if (kt >= 16)
                    mma16816((kt & 1) ? a0o : a0e, wreg0[kt - 16], b0, b1);
            }
            int col = nt * 8 + 2 * ctid;
            int row = wid * 16 + gid;
            sG1[row * 17 + col]           = a1e[0] + a1o[0];
            sG1[row * 17 + col + 1]       = a1e[1] + a1o[1];
            sG1[(row + 8) * 17 + col]     = a1e[2] + a1o[2];
            sG1[(row + 8) * 17 + col + 1] = a1e[3] + a1o[3];
            sG0[row * 17 + col]           = a0e[0] + a0o[0];
            sG0[row * 17 + col + 1]       = a0e[1] + a0o[1];
            sG0[(row + 8) * 17 + col]     = a0e[2] + a0o[2];
            sG0[(row + 8) * 17 + col + 1] = a0e[3] + a0o[3];
        }
        __syncthreads();

        const int j0 = 2 * jj, j1 = j0 + 1;

        // ---- cell0 + paired h0 publish ----
        if (do0) {
            float gi0 = xgA.x + sG0[(0  + j0) * 17 + m_act];
            float gi1 = xgA.y + sG0[(0  + j1) * 17 + m_act];
            float gf0 = xgA.z + sG0[(32 + j0) * 17 + m_act];
            float gf1 = xgA.w + sG0[(32 + j1) * 17 + m_act];
            float gg0 = xgB.x + sG0[(64 + j0) * 17 + m_act];
            float gg1 = xgB.y + sG0[(64 + j1) * 17 + m_act];
            float go0 = xgB.z + sG0[(96 + j0) * 17 + m_act];
            float go1 = xgB.w + sG0[(96 + j1) * 17 + m_act];
            c00 = sigm(gf0) * c00 + sigm(gi0) * tanhap(gg0);
            float h0 = sigm(go0) * tanhap(c00);
            c01 = sigm(gf1) * c01 + sigm(gi1) * tanhap(gg1);
            float h1 = sigm(go1) * tanhap(c01);
            __half2 hp = __floats2half2_rn(h0, h1);
            unsigned hv = *(unsigned*)&hp;
            unsigned pv = __shfl_xor_sync(0xffffffffu, hv, 1);
            uint64_t dv = (lane & 1) ? ((((uint64_t)hv) << 32) | pv)
                                     : ((((uint64_t)pv) << 32) | hv);
            const unsigned add_ = wb16 + 512u;
#pragma unroll
            for (int i = 0; i < 4; i++) {
                asm volatile("st.shared::cluster.u64 [%0], %1;"
                             :: "r"(rb4[i] + add_), "l"(dv) : "memory");
            }
            xgA = pA; xgB = pB;
        }

        // ---- cell1 + paired h1 publish (or final output) ----
        if (do1) {
            float gi0 = sG1[(0  + j0) * 17 + m_act] + sB1[0  + j0];
            float gi1 = sG1[(0  + j1) * 17 + m_act] + sB1[0  + j1];
            float gf0 = sG1[(32 + j0) * 17 + m_act] + sB1[32 + j0];
            float gf1 = sG1[(32 + j1) * 17 + m_act] + sB1[32 + j1];
            float gg0 = sG1[(64 + j0) * 17 + m_act] + sB1[64 + j0];
            float gg1 = sG1[(64 + j1) * 17 + m_act] + sB1[64 + j1];
            float go0 = sG1[(96 + j0) * 17 + m_act] + sB1[96 + j0];
            float go1 = sG1[(96 + j1) * 17 + m_act] + sB1[96 + j1];
            c10 = sigm(gf0) * c10 + sigm(gi0) * tanhap(gg0);
            float h0 = sigm(go0) * tanhap(c10);
            c11 = sigm(gf1) * c11 + sigm(gi1) * tanhap(gg1);
            float h1 = sigm(go1) * tanhap(c11);
            if (s < T_) {
                __half2 hp = __floats2half2_rn(h0, h1);
                unsigned hv = *(unsigned*)&hp;
                unsigned pv = __shfl_xor_sync(0xffffffffu, hv, 1);
                uint64_t dv = (lane & 1) ? ((((uint64_t)hv) << 32) | pv)
                                         : ((((uint64_t)pv) << 32) | hv);
#pragma unroll
                for (int i = 0; i < 4; i++) {
                    asm volatile("st.shared::cluster.u64 [%0], %1;"
                                 :: "r"(rb4[i] + wb16), "l"(dv) : "memory");
                }
            } else {
                g_h2last[(bm0 + m_act) * H_ + rank * 32 + j0] = h0;
                g_h2last[(bm0 + m_act) * H_ + rank * 32 + j1] = h1;
            }
        }

        if (s < T_) {
            asm volatile("barrier.cluster.arrive.aligned;" ::: "memory");
            asm volatile("barrier.cluster.wait.aligned;" ::: "memory");
        }
    }
}

// ---------------- FC head ----------------
__global__ void head_kernel(const float* __restrict__ W1, const float* __restrict__ b1,
                            const float* __restrict__ W2, const float* __restrict__ b2,
                            float* __restrict__ out) {
    __shared__ float sLast[4][H_];
    __shared__ float sZ[4][5 * H_ + 4];
    int b0 = blockIdx.x * 4, tid = threadIdx.x;
#pragma unroll
    for (int i = 0; i < 4; i++) sLast[i][tid] = g_h2last[(b0 + i) * H_ + tid];
    __syncthreads();
#pragma unroll
    for (int q = 0; q < 5; q++) {
        int j = q * 256 + tid;
        const float* wr = W1 + (size_t)j * H_;
        float a0 = 0.f, a1 = 0.f, a2 = 0.f, a3 = 0.f;
#pragma unroll 8
        for (int k = 0; k < H_; k += 4) {
            float4 w = *(const float4*)&wr[k];
            a0 += w.x * sLast[0][k] + w.y * sLast[0][k+1] + w.z * sLast[0][k+2] + w.w * sLast[0][k+3];
            a1 += w.x * sLast[1][k] + w.y * sLast[1][k+1] + w.z * sLast[1][k+2] + w.w * sLast[1][k+3];
            a2 += w.x * sLast[2][k] + w.y * sLast[2][k+1] + w.z * sLast[2][k+2] + w.w * sLast[2][k+3];
            a3 += w.x * sLast[3][k] + w.y * sLast[3][k+1] + w.z * sLast[3][k+2] + w.w * sLast[3][k+3];
        }
        float bb = b1[j];
        sZ[0][j] = a0 + bb; sZ[1][j] = a1 + bb; sZ[2][j] = a2 + bb; sZ[3][j] = a3 + bb;
    }
    __syncthreads();
    int w = tid >> 5, l = tid & 31;
#pragma unroll
    for (int pp = 0; pp < 2; pp++) {
        int p = w + pp * 8;
        int b = p >> 2, o = p & 3;
        float acc = 0.f;
        for (int i = l; i < 1280; i += 32) acc += sZ[b][i] * W2[o * 1280 + i];
#pragma unroll
        for (int s = 16; s; s >>= 1) acc += __shfl_xor_sync(0xffffffffu, acc, s);
        if (l == 0) out[(b0 + b) * 4 + o] = acc + b2[o];
    }
}

// ---------------- launch ----------------
extern "C" void kernel_launch(void* const* d_in, const int* in_sizes, int n_in,
                              void* d_out, int out_size) {
    const float* x    = (const float*)d_in[0];
    const float* Wih0 = (const float*)d_in[1];
    const float* Whh0 = (const float*)d_in[2];
    const float* bih0 = (const float*)d_in[3];
    const float* bhh0 = (const float*)d_in[4];
    const float* Wih1 = (const float*)d_in[5];
    const float* Whh1 = (const float*)d_in[6];
    const float* bih1 = (const float*)d_in[7];
    const float* bhh1 = (const float*)d_in[8];
    const float* W1   = (const float*)d_in[9];
    const float* b1   = (const float*)d_in[10];
    const float* W2   = (const float*)d_in[11];
    const float* b2   = (const float*)d_in[12];

    constexpr int SMG = NLOC * 144 + MR * 144 + (NLOC * 17 + NLOC) * 4;   // 29952
    constexpr int SMF = 184320;

    cudaFuncSetAttribute(xg_gemm64, cudaFuncAttributeMaxDynamicSharedMemorySize, SMG);
    cudaFuncSetAttribute(lstm_fused, cudaFuncAttributeMaxDynamicSharedMemorySize, SMF);

    prep_kernel<<<2048, 64>>>(Wih0, Whh0, bih0, bhh0, Wih1, Whh1, bih1, bhh1);
    xg_gemm64<<<dim3(128, T_ / TCH), 256, SMG>>>(x);
    lstm_fused<<<128, 256, SMF>>>();
    head_kernel<<<64, 256>>>(W1, b1, W2, b2, (float*)d_out);
}

// round 15
// speedup vs baseline: 1.5083x; 1.5083x over previous
#include <cuda_runtime.h>
#include <cuda_fp16.h>
#include <cstdint>
#include <cstddef>

#define B_ 256
#define T_ 512
#define H_ 256
#define I_ 64
#define CSZ 8
#define MR 16
#define NLOC 128
#define TCH 32

// ---------------- device scratch ----------------
__device__ float  g_h2last[B_ * H_];
__device__ __half g_whh0[CSZ * NLOC * 256];    // L0 recurrent weights, rank-sliced
__device__ __half g_w1cat[CSZ * NLOC * 512];   // L1 [Whh1|Wih1] rows, rank-sliced
__device__ __half g_wih0[CSZ * NLOC * 64];
__device__ float  g_bias0[CSZ * NLOC];
__device__ float  g_bias1[CSZ * NLOC];
__device__ int    g_probe;
// Precomputed L0 input-gate terms (bias folded): [cta(128), t(512), tid(256), 8]
__device__ float  g_xg0[(size_t)128 * 512 * 256 * 8];

// ---------------- helpers ----------------
__device__ __forceinline__ unsigned su32(const void* p) {
    unsigned a;
    asm("{ .reg .u64 t; cvta.to.shared.u64 t, %1; cvt.u32.u64 %0, t; }" : "=r"(a) : "l"(p));
    return a;
}
__device__ __forceinline__ float tanhap(float x) {
    float y;
    asm("tanh.approx.f32 %0, %1;" : "=f"(y) : "f"(x));
    return y;
}
__device__ __forceinline__ float sigm(float x) {
    return fmaf(tanhap(0.5f * x), 0.5f, 0.5f);
}
__device__ __forceinline__ void ldsm_x2(uint32_t& b0, uint32_t& b1, unsigned a) {
    asm volatile("ldmatrix.sync.aligned.m8n8.x2.shared.b16 {%0,%1}, [%2];"
                 : "=r"(b0), "=r"(b1) : "r"(a));
}
__device__ __forceinline__ void ldsm_x4(uint32_t* r, unsigned a) {
    asm volatile("ldmatrix.sync.aligned.m8n8.x4.shared.b16 {%0,%1,%2,%3}, [%4];"
                 : "=r"(r[0]), "=r"(r[1]), "=r"(r[2]), "=r"(r[3]) : "r"(a));
}
__device__ __forceinline__ void mma16816(float* acc, const uint32_t* a, uint32_t b0, uint32_t b1) {
    asm volatile(
        "mma.sync.aligned.m16n8k16.row.col.f32.f16.f16.f32 "
        "{%0,%1,%2,%3}, {%4,%5,%6,%7}, {%8,%9}, {%0,%1,%2,%3};"
        : "+f"(acc[0]), "+f"(acc[1]), "+f"(acc[2]), "+f"(acc[3])
        : "r"(a[0]), "r"(a[1]), "r"(a[2]), "r"(a[3]), "r"(b0), "r"(b1));
}

// ---------------- probe (shifts launch index so ncu captures lstm_fused) ----------------
__global__ void probe_kernel() {
    if (threadIdx.x == 0) g_probe = (int)blockIdx.x + 1;
}

// ---------------- weight prep ----------------
// Local row l of rank r: gate g = l>>5, h-col = r*32 + (l&31), grow = g*256 + r*32 + (l&31).
__global__ void prep_kernel(const float* __restrict__ Wih0, const float* __restrict__ Whh0,
                            const float* __restrict__ bih0, const float* __restrict__ bhh0,
                            const float* __restrict__ Wih1, const float* __restrict__ Whh1,
                            const float* __restrict__ bih1, const float* __restrict__ bhh1) {
    int blk = blockIdx.x;
    int li = blk & 1023;
    int r = li >> 7, l = li & 127;
    int grow = (l >> 5) * H_ + r * 32 + (l & 31);
    if (blk < 1024) {
        for (int k = threadIdx.x; k < 256; k += blockDim.x)
            g_whh0[(r * NLOC + l) * 256 + k] = __float2half_rn(Whh0[grow * H_ + k]);
        for (int k = threadIdx.x; k < 64; k += blockDim.x)
            g_wih0[(r * NLOC + l) * 64 + k] = __float2half_rn(Wih0[grow * I_ + k]);
        if (threadIdx.x == 0) g_bias0[r * NLOC + l] = bih0[grow] + bhh0[grow];
    } else {
        for (int k = threadIdx.x; k < 512; k += blockDim.x) {
            float v = (k < 256) ? Whh1[grow * H_ + k] : Wih1[grow * H_ + (k - 256)];
            g_w1cat[(r * NLOC + l) * 512 + k] = __float2half_rn(v);
        }
        if (threadIdx.x == 0) g_bias1[r * NLOC + l] = bih1[grow] + bhh1[grow];
    }
}

// ---------------- time-parallel L0 input GEMM: xg0[cta,t,tid,0:8] ----------------
__global__ void __launch_bounds__(256) xg_gemm64(const float* __restrict__ xin) {
    constexpr int KT  = 4;
    constexpr int KPB = (64 + 8) * 2;   // 144

    extern __shared__ __align__(16) char smem[];
    char*  sW    = smem;
    char*  sB    = sW + NLOC * KPB;
    float* sG    = (float*)(sB + MR * KPB);
    float* sBias = sG + NLOC * 17;

    const int tid  = threadIdx.x;
    const int wid  = tid >> 5;
    const int lane = tid & 31;
    const int rank = blockIdx.x & 7;
    const int bm0  = (blockIdx.x >> 3) * MR;
    const int t0   = blockIdx.y * TCH;

    {
        const uint4* src = (const uint4*)(g_wih0 + (size_t)rank * NLOC * 64);
        for (int i = tid; i < NLOC * 8; i += 256) {
            int l = i >> 3, c = i & 7;
            *(uint4*)(sW + l * KPB + c * 16) = src[i];
        }
    }
    if (tid < NLOC) sBias[tid] = g_bias0[rank * NLOC + tid];
    __syncthreads();

    uint32_t wreg[KT][4];
    {
        unsigned rb = su32(sW) + (unsigned)(wid * 16 + (lane & 15)) * KPB + ((lane & 16) ? 16u : 0u);
#pragma unroll
        for (int kt = 0; kt < KT; kt++) ldsm_x4(wreg[kt], rb + kt * 32);
    }

    const unsigned sBu = su32(sB);
    const unsigned boffL = (unsigned)((lane & 7) * KPB) + ((lane & 8) ? 16u : 0u);
    const int gid = lane >> 2, ctid = lane & 3;
    const int m_act = tid >> 4, jj = tid & 15;
    const int mx = tid >> 4, cx = tid & 15;

    for (int tt = 0; tt < TCH; tt++) {
        const int t = t0 + tt;
        float4 v = *(const float4*)&xin[((size_t)(bm0 + mx) * T_ + t) * I_ + cx * 4];
        __half2* d = (__half2*)(sB + mx * KPB + cx * 8);
        d[0] = __floats2half2_rn(v.x, v.y);
        d[1] = __floats2half2_rn(v.z, v.w);
        __syncthreads();

        float accA[2][4] = {{0.f,0.f,0.f,0.f},{0.f,0.f,0.f,0.f}};
#pragma unroll
        for (int nt = 0; nt < 2; nt++) {
            unsigned bb = sBu + (unsigned)(nt * 8) * KPB + boffL;
#pragma unroll
            for (int kt = 0; kt < KT; kt++) {
                uint32_t b0, b1;
                ldsm_x2(b0, b1, bb + kt * 32);
                mma16816(accA[nt], wreg[kt], b0, b1);
            }
        }
#pragma unroll
        for (int nt = 0; nt < 2; nt++) {
            int col = nt * 8 + 2 * ctid;
            int row = wid * 16 + gid;
            sG[row * 17 + col]           = accA[nt][0];
            sG[row * 17 + col + 1]       = accA[nt][1];
            sG[(row + 8) * 17 + col]     = accA[nt][2];
            sG[(row + 8) * 17 + col + 1] = accA[nt][3];
        }
        __syncthreads();
        {
            int j0 = 2 * jj, j1 = j0 + 1;
            float4 oA, oB;
            oA.x = sG[(0  + j0) * 17 + m_act] + sBias[0  + j0];
            oA.y = sG[(0  + j1) * 17 + m_act] + sBias[0  + j1];
            oA.z = sG[(32 + j0) * 17 + m_act] + sBias[32 + j0];
            oA.w = sG[(32 + j1) * 17 + m_act] + sBias[32 + j1];
            oB.x = sG[(64 + j0) * 17 + m_act] + sBias[64 + j0];
            oB.y = sG[(64 + j1) * 17 + m_act] + sBias[64 + j1];
            oB.z = sG[(96 + j0) * 17 + m_act] + sBias[96 + j0];
            oB.w = sG[(96 + j1) * 17 + m_act] + sBias[96 + j1];
            size_t base = (((size_t)blockIdx.x * T_ + t) * 256 + tid) * 8;
            *(float4*)&g_xg0[base]     = oA;
            *(float4*)&g_xg0[base + 4] = oB;
        }
        __syncthreads();
    }
}

// ---------------- fused 2-layer wavefront loop (R9 structure) ----------------
// Cluster of 8 CTAs = one batch group (16 rows). Rank r owns gate rows
// {g*256 + r*32 + j} and h-cols [r*32, r*32+32) for BOTH layers.
// Both weight sets in REGISTERS; one B-frag stream over hcat [h1|h0] feeds both
// GEMMs, now fetched as ldsm_x4 (two k-tiles per instruction).
__global__ void __launch_bounds__(256, 1) __cluster_dims__(CSZ, 1, 1)
lstm_fused() {
    constexpr int W1B   = 1040;            // W1cat / hcat row stride bytes (520 halves)
    constexpr int HCB   = MR * W1B;        // one hcat buffer = 16640 B
    constexpr int HC_OFF = NLOC * W1B;     // 133120
    constexpr int SG0_OFF = HC_OFF + 2 * HCB;          // 166400
    constexpr int SG1_OFF = SG0_OFF + NLOC * 17 * 4;   // 175104
    constexpr int SB1_OFF = SG1_OFF + NLOC * 17 * 4;   // 183808

    extern __shared__ __align__(16) char smem[];
    char*  sW1 = smem;                     // init-only staging
    char*  sHC = smem + HC_OFF;
    float* sG0 = (float*)(smem + SG0_OFF);
    float* sG1 = (float*)(smem + SG1_OFF);
    float* sB1 = (float*)(smem + SB1_OFF);

    const int tid  = threadIdx.x;
    const int wid  = tid >> 5;
    const int lane = tid & 31;
    unsigned rank;
    asm("mov.u32 %0, %%cluster_ctarank;" : "=r"(rank));
    const int bm0 = (blockIdx.x >> 3) * MR;

    const unsigned arow = (unsigned)(wid * 16 + (lane & 15)) * W1B + ((lane & 16) ? 16u : 0u);

    // ---- Phase A: stage Whh0 temporarily into sW1 region, grab wreg0 ----
    {
        const uint4* s0 = (const uint4*)(g_whh0 + (size_t)rank * NLOC * 256);
        for (int i = tid; i < NLOC * 32; i += 256) {
            int l = i >> 5, c = i & 31;
            *(uint4*)(sW1 + l * 528 + c * 16) = s0[i];
        }
    }
    __syncthreads();
    uint32_t wreg0[16][4];
    {
        unsigned rb = su32(sW1) + (unsigned)(wid * 16 + (lane & 15)) * 528 + ((lane & 16) ? 16u : 0u);
#pragma unroll
        for (int kt = 0; kt < 16; kt++) ldsm_x4(wreg0[kt], rb + kt * 32);
    }
    __syncthreads();

    // ---- Phase B: stage W1cat into sW1, grab wreg1, then sW1 is dead ----
    {
        const uint4* src = (const uint4*)(g_w1cat + (size_t)rank * NLOC * 512);
        for (int i = tid; i < NLOC * 64; i += 256) {
            int l = i >> 6, c = i & 63;
            *(uint4*)(sW1 + l * W1B + c * 16) = src[i];
        }
    }
    __syncthreads();
    uint32_t wreg1[32][4];
    {
        unsigned aW = su32(sW1) + arow;
#pragma unroll
        for (int kt = 0; kt < 32; kt++) ldsm_x4(wreg1[kt], aW + kt * 32);
    }
    __syncthreads();

    // ---- Phase C: zero hcat buffers, load bias ----
    for (int i = tid; i < 2 * HCB / 4; i += 256) ((unsigned*)sHC)[i] = 0u;
    if (tid < NLOC) sB1[tid] = g_bias1[rank * NLOC + tid];

    const unsigned sHCu = su32(sHC);
    // x4 B-frag lane offsets: lanes 0-7 -> kt frag0, 8-15 -> kt frag1,
    // 16-23 -> kt+1 frag0 (+32B), 24-31 -> kt+1 frag1 (+48B)
    const unsigned hoff4 = (unsigned)((lane & 7) * W1B) + (unsigned)((lane >> 3) * 16);
    const int gid = lane >> 2, ctid = lane & 3;
    const int m_act = tid >> 4, jj = tid & 15;

    // ---- DSMEM publish offsets (u32 stores, mapa inline — the R9 pattern) ----
    const unsigned offh = sHCu + (unsigned)(m_act * W1B + (rank * 32 + 2 * jj) * 2);  // h1 slot
    const unsigned offx = offh + 512u;                                                // h0 slot

    // xg0 stream
    const float4* xg4 = (const float4*)g_xg0;
    const size_t xbase = ((size_t)blockIdx.x * T_) * 512 + tid * 2;
    float4 xgA = xg4[xbase], xgB = xg4[xbase + 1];

    float c00 = 0.f, c01 = 0.f, c10 = 0.f, c11 = 0.f;

    __syncthreads();
    asm volatile("barrier.cluster.arrive.aligned;" ::: "memory");
    asm volatile("barrier.cluster.wait.aligned;" ::: "memory");

#pragma unroll 1
    for (int s = 0; s <= T_; s++) {
        const unsigned rb16 = (unsigned)((s & 1) * HCB);
        const unsigned wb16 = rb16 ^ (unsigned)HCB;
        const bool do0 = (s < T_);
        const bool do1 = (s >= 1);

        // prefetch xg[s+1]
        float4 pA, pB;
        if (do0) {
            int tn = (s + 1 < T_) ? s + 1 : s;
            pA = xg4[xbase + (size_t)tn * 512];
            pB = xg4[xbase + (size_t)tn * 512 + 1];
        }

        // ---- merged GEMMs: one x4 B stream feeds both ----
#pragma unroll
        for (int nt = 0; nt < 2; nt++) {
            float a1e[4] = {0,0,0,0}, a1o[4] = {0,0,0,0};
            float a0e[4] = {0,0,0,0}, a0o[4] = {0,0,0,0};
            unsigned hb = sHCu + rb16 + hoff4 + (unsigned)(nt * 8) * W1B;
#pragma unroll
            for (int ktp = 0; ktp < 16; ktp++) {
                uint32_t b[4];
                ldsm_x4(b, hb + ktp * 64);
                const int kt = 2 * ktp;
                mma16816(a1e, wreg1[kt],     b[0], b[1]);
                mma16816(a1o, wreg1[kt + 1], b[2], b[3]);
                if (kt >= 16) {
                    mma16816(a0e, wreg0[kt - 16], b[0], b[1]);
                    mma16816(a0o, wreg0[kt - 15], b[2], b[3]);
                }
            }
            int col = nt * 8 + 2 * ctid;
            int row = wid * 16 + gid;
            sG1[row * 17 + col]           = a1e[0] + a1o[0];
            sG1[row * 17 + col + 1]       = a1e[1] + a1o[1];
            sG1[(row + 8) * 17 + col]     = a1e[2] + a1o[2];
            sG1[(row + 8) * 17 + col + 1] = a1e[3] + a1o[3];
            sG0[row * 17 + col]           = a0e[0] + a0o[0];
            sG0[row * 17 + col + 1]       = a0e[1] + a0o[1];
            sG0[(row + 8) * 17 + col]     = a0e[2] + a0o[2];
            sG0[(row + 8) * 17 + col + 1] = a0e[3] + a0o[3];
        }
        __syncthreads();

        const int j0 = 2 * jj, j1 = j0 + 1;

        // ---- cell0 + h0 publish ----
        if (do0) {
            float gi0 = xgA.x + sG0[(0  + j0) * 17 + m_act];
            float gi1 = xgA.y + sG0[(0  + j1) * 17 + m_act];
            float gf0 = xgA.z + sG0[(32 + j0) * 17 + m_act];
            float gf1 = xgA.w + sG0[(32 + j1) * 17 + m_act];
            float gg0 = xgB.x + sG0[(64 + j0) * 17 + m_act];
            float gg1 = xgB.y + sG0[(64 + j1) * 17 + m_act];
            float go0 = xgB.z + sG0[(96 + j0) * 17 + m_act];
            float go1 = xgB.w + sG0[(96 + j1) * 17 + m_act];
            c00 = sigm(gf0) * c00 + sigm(gi0) * tanhap(gg0);
            float h0 = sigm(go0) * tanhap(c00);
            c01 = sigm(gf1) * c01 + sigm(gi1) * tanhap(gg1);
            float h1 = sigm(go1) * tanhap(c01);
            __half2 hp = __floats2half2_rn(h0, h1);
            unsigned hv = *(unsigned*)&hp;
            const unsigned src_ = offx + wb16;
#pragma unroll
            for (int rr = 0; rr < CSZ; rr++) {
                unsigned ra;
                asm volatile("mapa.shared::cluster.u32 %0, %1, %2;" : "=r"(ra) : "r"(src_), "r"(rr));
                asm volatile("st.shared::cluster.u32 [%0], %1;" :: "r"(ra), "r"(hv) : "memory");
            }
            xgA = pA; xgB = pB;
        }

        // ---- cell1 + h1 publish (or final output) ----
        if (do1) {
            float gi0 = sG1[(0  + j0) * 17 + m_act] + sB1[0  + j0];
            float gi1 = sG1[(0  + j1) * 17 + m_act] + sB1[0  + j1];
            float gf0 = sG1[(32 + j0) * 17 + m_act] + sB1[32 + j0];
            float gf1 = sG1[(32 + j1) * 17 + m_act] + sB1[32 + j1];
            float gg0 = sG1[(64 + j0) * 17 + m_act] + sB1[64 + j0];
            float gg1 = sG1[(64 + j1) * 17 + m_act] + sB1[64 + j1];
            float go0 = sG1[(96 + j0) * 17 + m_act] + sB1[96 + j0];
            float go1 = sG1[(96 + j1) * 17 + m_act] + sB1[96 + j1];
            c10 = sigm(gf0) * c10 + sigm(gi0) * tanhap(gg0);
            float h0 = sigm(go0) * tanhap(c10);
            c11 = sigm(gf1) * c11 + sigm(gi1) * tanhap(gg1);
            float h1 = sigm(go1) * tanhap(c11);
            if (s < T_) {
                __half2 hp = __floats2half2_rn(h0, h1);
                unsigned hv = *(unsigned*)&hp;
                const unsigned src_ = offh + wb16;
#pragma unroll
                for (int rr = 0; rr < CSZ; rr++) {
                    unsigned ra;
                    asm volatile("mapa.shared::cluster.u32 %0, %1, %2;" : "=r"(ra) : "r"(src_), "r"(rr));
                    asm volatile("st.shared::cluster.u32 [%0], %1;" :: "r"(ra), "r"(hv) : "memory");
                }
            } else {
                g_h2last[(bm0 + m_act) * H_ + rank * 32 + j0] = h0;
                g_h2last[(bm0 + m_act) * H_ + rank * 32 + j1] = h1;
            }
        }

        if (s < T_) {
            asm volatile("barrier.cluster.arrive.aligned;" ::: "memory");
            asm volatile("barrier.cluster.wait.aligned;" ::: "memory");
        }
    }
}

// ---------------- FC head ----------------
__global__ void head_kernel(const float* __restrict__ W1, const float* __restrict__ b1,
                            const float* __restrict__ W2, const float* __restrict__ b2,
                            float* __restrict__ out) {
    __shared__ float sLast[4][H_];
    __shared__ float sZ[4][5 * H_ + 4];
    int b0 = blockIdx.x * 4, tid = threadIdx.x;
#pragma unroll
    for (int i = 0; i < 4; i++) sLast[i][tid] = g_h2last[(b0 + i) * H_ + tid];
    __syncthreads();
#pragma unroll
    for (int q = 0; q < 5; q++) {
        int j = q * 256 + tid;
        const float* wr = W1 + (size_t)j * H_;
        float a0 = 0.f, a1 = 0.f, a2 = 0.f, a3 = 0.f;
#pragma unroll 8
        for (int k = 0; k < H_; k += 4) {
            float4 w = *(const float4*)&wr[k];
            a0 += w.x * sLast[0][k] + w.y * sLast[0][k+1] + w.z * sLast[0][k+2] + w.w * sLast[0][k+3];
            a1 += w.x * sLast[1][k] + w.y * sLast[1][k+1] + w.z * sLast[1][k+2] + w.w * sLast[1][k+3];
            a2 += w.x * sLast[2][k] + w.y * sLast[2][k+1] + w.z * sLast[2][k+2] + w.w * sLast[2][k+3];
            a3 += w.x * sLast[3][k] + w.y * sLast[3][k+1] + w.z * sLast[3][k+2] + w.w * sLast[3][k+3];
        }
        float bb = b1[j];
        sZ[0][j] = a0 + bb; sZ[1][j] = a1 + bb; sZ[2][j] = a2 + bb; sZ[3][j] = a3 + bb;
    }
    __syncthreads();
    int w = tid >> 5, l = tid & 31;
#pragma unroll
    for (int pp = 0; pp < 2; pp++) {
        int p = w + pp * 8;
        int b = p >> 2, o = p & 3;
        float acc = 0.f;
        for (int i = l; i < 1280; i += 32) acc += sZ[b][i] * W2[o * 1280 + i];
#pragma unroll
        for (int s = 16; s; s >>= 1) acc += __shfl_xor_sync(0xffffffffu, acc, s);
        if (l == 0) out[(b0 + b) * 4 + o] = acc + b2[o];
    }
}

// ---------------- launch ----------------
extern "C" void kernel_launch(void* const* d_in, const int* in_sizes, int n_in,
                              void* d_out, int out_size) {
    const float* x    = (const float*)d_in[0];
    const float* Wih0 = (const float*)d_in[1];
    const float* Whh0 = (const float*)d_in[2];
    const float* bih0 = (const float*)d_in[3];
    const float* bhh0 = (const float*)d_in[4];
    const float* Wih1 = (const float*)d_in[5];
    const float* Whh1 = (const float*)d_in[6];
    const float* bih1 = (const float*)d_in[7];
    const float* bhh1 = (const float*)d_in[8];
    const float* W1   = (const float*)d_in[9];
    const float* b1   = (const float*)d_in[10];
    const float* W2   = (const float*)d_in[11];
    const float* b2   = (const float*)d_in[12];

    constexpr int SMG = NLOC * 144 + MR * 144 + (NLOC * 17 + NLOC) * 4;   // 29952
    constexpr int SMF = 184320;

    cudaFuncSetAttribute(xg_gemm64, cudaFuncAttributeMaxDynamicSharedMemorySize, SMG);
    cudaFuncSetAttribute(lstm_fused, cudaFuncAttributeMaxDynamicSharedMemorySize, SMF);

    prep_kernel<<<2048, 64>>>(Wih0, Whh0, bih0, bhh0, Wih1, Whh1, bih1, bhh1);     // launch 0
    xg_gemm64<<<dim3(128, T_ / TCH), 256, SMG>>>(x);                               // launch 1
    probe_kernel<<<1, 32>>>();                                                     // launch 2
    lstm_fused<<<128, 256, SMF>>>();                                               // launch 3 <- ncu capture slot
    head_kernel<<<64, 256>>>(W1, b1, W2, b2, (float*)d_out);                       // launch 4
}

// round 16
// speedup vs baseline: 1.5549x; 1.0309x over previous
#include <cuda_runtime.h>
#include <cuda_fp16.h>
#include <cstdint>
#include <cstddef>

#define B_ 256
#define T_ 512
#define H_ 256
#define I_ 64
#define CSZ 8
#define MR 16
#define NLOC 128
#define TCH 32

// ---------------- device scratch ----------------
__device__ float  g_h2last[B_ * H_];
__device__ __half g_whh0[CSZ * NLOC * 256];    // L0 recurrent weights, rank-sliced
__device__ __half g_w1cat[CSZ * NLOC * 512];   // L1 [Whh1|Wih1] rows, rank-sliced
__device__ __half g_wih0[CSZ * NLOC * 64];
__device__ float  g_bias0[CSZ * NLOC];
__device__ float  g_bias1[CSZ * NLOC];
__device__ int    g_probe;
// Precomputed L0 input-gate terms (bias folded): [cta(128), t(512), tid(256), 8]
__device__ float  g_xg0[(size_t)128 * 512 * 256 * 8];

// ---------------- helpers ----------------
__device__ __forceinline__ unsigned su32(const void* p) {
    unsigned a;
    asm("{ .reg .u64 t; cvta.to.shared.u64 t, %1; cvt.u32.u64 %0, t; }" : "=r"(a) : "l"(p));
    return a;
}
__device__ __forceinline__ float tanhap(float x) {
    float y;
    asm("tanh.approx.f32 %0, %1;" : "=f"(y) : "f"(x));
    return y;
}
__device__ __forceinline__ float sigm(float x) {
    return fmaf(tanhap(0.5f * x), 0.5f, 0.5f);
}
__device__ __forceinline__ void ldsm_x2(uint32_t& b0, uint32_t& b1, unsigned a) {
    asm volatile("ldmatrix.sync.aligned.m8n8.x2.shared.b16 {%0,%1}, [%2];"
                 : "=r"(b0), "=r"(b1) : "r"(a));
}
__device__ __forceinline__ void ldsm_x4(uint32_t* r, unsigned a) {
    asm volatile("ldmatrix.sync.aligned.m8n8.x4.shared.b16 {%0,%1,%2,%3}, [%4];"
                 : "=r"(r[0]), "=r"(r[1]), "=r"(r[2]), "=r"(r[3]) : "r"(a));
}
__device__ __forceinline__ void mma16816(float* acc, const uint32_t* a, uint32_t b0, uint32_t b1) {
    asm volatile(
        "mma.sync.aligned.m16n8k16.row.col.f32.f16.f16.f32 "
        "{%0,%1,%2,%3}, {%4,%5,%6,%7}, {%8,%9}, {%0,%1,%2,%3};"
        : "+f"(acc[0]), "+f"(acc[1]), "+f"(acc[2]), "+f"(acc[3])
        : "r"(a[0]), "r"(a[1]), "r"(a[2]), "r"(a[3]), "r"(b0), "r"(b1));
}

// ---------------- probe (keeps lstm_fused in the ncu capture slot) ----------------
__global__ void probe_kernel() {
    if (threadIdx.x == 0) g_probe = (int)blockIdx.x + 1;
}

// ---------------- weight prep ----------------
// Local row l of rank r: gate g = l>>5, h-col = r*32 + (l&31), grow = g*256 + r*32 + (l&31).
__global__ void prep_kernel(const float* __restrict__ Wih0, const float* __restrict__ Whh0,
                            const float* __restrict__ bih0, const float* __restrict__ bhh0,
                            const float* __restrict__ Wih1, const float* __restrict__ Whh1,
                            const float* __restrict__ bih1, const float* __restrict__ bhh1) {
    int blk = blockIdx.x;
    int li = blk & 1023;
    int r = li >> 7, l = li & 127;
    int grow = (l >> 5) * H_ + r * 32 + (l & 31);
    if (blk < 1024) {
        for (int k = threadIdx.x; k < 256; k += blockDim.x)
            g_whh0[(r * NLOC + l) * 256 + k] = __float2half_rn(Whh0[grow * H_ + k]);
        for (int k = threadIdx.x; k < 64; k += blockDim.x)
            g_wih0[(r * NLOC + l) * 64 + k] = __float2half_rn(Wih0[grow * I_ + k]);
        if (threadIdx.x == 0) g_bias0[r * NLOC + l] = bih0[grow] + bhh0[grow];
    } else {
        for (int k = threadIdx.x; k < 512; k += blockDim.x) {
            float v = (k < 256) ? Whh1[grow * H_ + k] : Wih1[grow * H_ + (k - 256)];
            g_w1cat[(r * NLOC + l) * 512 + k] = __float2half_rn(v);
        }
        if (threadIdx.x == 0) g_bias1[r * NLOC + l] = bih1[grow] + bhh1[grow];
    }
}

// ---------------- time-parallel L0 input GEMM: xg0[cta,t,tid,0:8] ----------------
__global__ void __launch_bounds__(256) xg_gemm64(const float* __restrict__ xin) {
    constexpr int KT  = 4;
    constexpr int KPB = (64 + 8) * 2;   // 144

    extern __shared__ __align__(16) char smem[];
    char*  sW    = smem;
    char*  sB    = sW + NLOC * KPB;
    float* sG    = (float*)(sB + MR * KPB);
    float* sBias = sG + NLOC * 17;

    const int tid  = threadIdx.x;
    const int wid  = tid >> 5;
    const int lane = tid & 31;
    const int rank = blockIdx.x & 7;
    const int bm0  = (blockIdx.x >> 3) * MR;
    const int t0   = blockIdx.y * TCH;

    {
        const uint4* src = (const uint4*)(g_wih0 + (size_t)rank * NLOC * 64);
        for (int i = tid; i < NLOC * 8; i += 256) {
            int l = i >> 3, c = i & 7;
            *(uint4*)(sW + l * KPB + c * 16) = src[i];
        }
    }
    if (tid < NLOC) sBias[tid] = g_bias0[rank * NLOC + tid];
    __syncthreads();

    uint32_t wreg[KT][4];
    {
        unsigned rb = su32(sW) + (unsigned)(wid * 16 + (lane & 15)) * KPB + ((lane & 16) ? 16u : 0u);
#pragma unroll
        for (int kt = 0; kt < KT; kt++) ldsm_x4(wreg[kt], rb + kt * 32);
    }

    const unsigned sBu = su32(sB);
    const unsigned boffL = (unsigned)((lane & 7) * KPB) + ((lane & 8) ? 16u : 0u);
    const int gid = lane >> 2, ctid = lane & 3;
    const int m_act = tid >> 4, jj = tid & 15;
    const int mx = tid >> 4, cx = tid & 15;

    for (int tt = 0; tt < TCH; tt++) {
        const int t = t0 + tt;
        float4 v = *(const float4*)&xin[((size_t)(bm0 + mx) * T_ + t) * I_ + cx * 4];
        __half2* d = (__half2*)(sB + mx * KPB + cx * 8);
        d[0] = __floats2half2_rn(v.x, v.y);
        d[1] = __floats2half2_rn(v.z, v.w);
        __syncthreads();

        float accA[2][4] = {{0.f,0.f,0.f,0.f},{0.f,0.f,0.f,0.f}};
#pragma unroll
        for (int nt = 0; nt < 2; nt++) {
            unsigned bb = sBu + (unsigned)(nt * 8) * KPB + boffL;
#pragma unroll
            for (int kt = 0; kt < KT; kt++) {
                uint32_t b0, b1;
                ldsm_x2(b0, b1, bb + kt * 32);
                mma16816(accA[nt], wreg[kt], b0, b1);
            }
        }
#pragma unroll
        for (int nt = 0; nt < 2; nt++) {
            int col = nt * 8 + 2 * ctid;
            int row = wid * 16 + gid;
            sG[row * 17 + col]           = accA[nt][0];
            sG[row * 17 + col + 1]       = accA[nt][1];
            sG[(row + 8) * 17 + col]     = accA[nt][2];
            sG[(row + 8) * 17 + col + 1] = accA[nt][3];
        }
        __syncthreads();
        {
            int j0 = 2 * jj, j1 = j0 + 1;
            float4 oA, oB;
            oA.x = sG[(0  + j0) * 17 + m_act] + sBias[0  + j0];
            oA.y = sG[(0  + j1) * 17 + m_act] + sBias[0  + j1];
            oA.z = sG[(32 + j0) * 17 + m_act] + sBias[32 + j0];
            oA.w = sG[(32 + j1) * 17 + m_act] + sBias[32 + j1];
            oB.x = sG[(64 + j0) * 17 + m_act] + sBias[64 + j0];
            oB.y = sG[(64 + j1) * 17 + m_act] + sBias[64 + j1];
            oB.z = sG[(96 + j0) * 17 + m_act] + sBias[96 + j0];
            oB.w = sG[(96 + j1) * 17 + m_act] + sBias[96 + j1];
            size_t base = (((size_t)blockIdx.x * T_ + t) * 256 + tid) * 8;
            *(float4*)&g_xg0[base]     = oA;
            *(float4*)&g_xg0[base + 4] = oB;
        }
        __syncthreads();
    }
}

// ---------------- fused 2-layer wavefront loop ----------------
// Cluster of 8 CTAs = one batch group (16 rows). Rank r owns gate rows
// {g*256 + r*32 + j} and h-cols [r*32, r*32+32) for BOTH layers.
// Both weight sets in REGISTERS; one x2-ldsm B stream over hcat [h1|h0] feeds both
// GEMMs. GEMM1 accumulates into 4 chains (kt&3) for mma ILP; kt walk runs the
// shared half (16..31) first so 6 chains are live early. xg[s+1] loads in the
// cluster-barrier arrive->wait window (no prefetch registers).
__global__ void __launch_bounds__(256, 1) __cluster_dims__(CSZ, 1, 1)
lstm_fused() {
    constexpr int W1B   = 1040;            // W1cat / hcat row stride bytes (520 halves)
    constexpr int HCB   = MR * W1B;        // one hcat buffer = 16640 B
    constexpr int HC_OFF = NLOC * W1B;     // 133120
    constexpr int SG0_OFF = HC_OFF + 2 * HCB;          // 166400
    constexpr int SG1_OFF = SG0_OFF + NLOC * 17 * 4;   // 175104
    constexpr int SB1_OFF = SG1_OFF + NLOC * 17 * 4;   // 183808

    extern __shared__ __align__(16) char smem[];
    char*  sW1 = smem;                     // init-only staging
    char*  sHC = smem + HC_OFF;
    float* sG0 = (float*)(smem + SG0_OFF);
    float* sG1 = (float*)(smem + SG1_OFF);
    float* sB1 = (float*)(smem + SB1_OFF);

    const int tid  = threadIdx.x;
    const int wid  = tid >> 5;
    const int lane = tid & 31;
    unsigned rank;
    asm("mov.u32 %0, %%cluster_ctarank;" : "=r"(rank));
    const int bm0 = (blockIdx.x >> 3) * MR;

    const unsigned arow = (unsigned)(wid * 16 + (lane & 15)) * W1B + ((lane & 16) ? 16u : 0u);

    // ---- Phase A: stage Whh0 temporarily into sW1 region, grab wreg0 ----
    {
        const uint4* s0 = (const uint4*)(g_whh0 + (size_t)rank * NLOC * 256);
        for (int i = tid; i < NLOC * 32; i += 256) {
            int l = i >> 5, c = i & 31;
            *(uint4*)(sW1 + l * 528 + c * 16) = s0[i];
        }
    }
    __syncthreads();
    uint32_t wreg0[16][4];
    {
        unsigned rb = su32(sW1) + (unsigned)(wid * 16 + (lane & 15)) * 528 + ((lane & 16) ? 16u : 0u);
#pragma unroll
        for (int kt = 0; kt < 16; kt++) ldsm_x4(wreg0[kt], rb + kt * 32);
    }
    __syncthreads();

    // ---- Phase B: stage W1cat into sW1, grab wreg1, then sW1 is dead ----
    {
        const uint4* src = (const uint4*)(g_w1cat + (size_t)rank * NLOC * 512);
        for (int i = tid; i < NLOC * 64; i += 256) {
            int l = i >> 6, c = i & 63;
            *(uint4*)(sW1 + l * W1B + c * 16) = src[i];
        }
    }
    __syncthreads();
    uint32_t wreg1[32][4];
    {
        unsigned aW = su32(sW1) + arow;
#pragma unroll
        for (int kt = 0; kt < 32; kt++) ldsm_x4(wreg1[kt], aW + kt * 32);
    }
    __syncthreads();

    // ---- Phase C: zero hcat buffers, load bias ----
    for (int i = tid; i < 2 * HCB / 4; i += 256) ((unsigned*)sHC)[i] = 0u;
    if (tid < NLOC) sB1[tid] = g_bias1[rank * NLOC + tid];

    const unsigned sHCu = su32(sHC);
    const unsigned hoffL = (unsigned)((lane & 7) * W1B) + ((lane & 8) ? 16u : 0u);
    const int gid = lane >> 2, ctid = lane & 3;
    const int m_act = tid >> 4, jj = tid & 15;

    // ---- DSMEM publish offsets (u32 stores, mapa inline) ----
    const unsigned offh = sHCu + (unsigned)(m_act * W1B + (rank * 32 + 2 * jj) * 2);  // h1 slot
    const unsigned offx = offh + 512u;                                                // h0 slot

    // xg0 stream (no prefetch regs; loaded in arrive->wait window)
    const float4* xg4 = (const float4*)g_xg0;
    const size_t xbase = ((size_t)blockIdx.x * T_) * 512 + tid * 2;
    float4 xgA = xg4[xbase], xgB = xg4[xbase + 1];

    float c00 = 0.f, c01 = 0.f, c10 = 0.f, c11 = 0.f;

    __syncthreads();
    asm volatile("barrier.cluster.arrive.aligned;" ::: "memory");
    asm volatile("barrier.cluster.wait.aligned;" ::: "memory");

#pragma unroll 1
    for (int s = 0; s <= T_; s++) {
        const unsigned rb16 = (unsigned)((s & 1) * HCB);
        const unsigned wb16 = rb16 ^ (unsigned)HCB;
        const bool do0 = (s < T_);
        const bool do1 = (s >= 1);

        // ---- merged GEMMs: one B stream feeds both; 4-chain GEMM1, 2-chain GEMM0 ----
#pragma unroll
        for (int nt = 0; nt < 2; nt++) {
            float a1[4][4] = {{0,0,0,0},{0,0,0,0},{0,0,0,0},{0,0,0,0}};
            float a0e[4] = {0,0,0,0}, a0o[4] = {0,0,0,0};
            unsigned hb = sHCu + rb16 + hoffL + (unsigned)(nt * 8) * W1B;
#pragma unroll
            for (int ktx = 0; ktx < 32; ktx++) {
                const int kt = (ktx + 16) & 31;    // shared half (16..31) first
                uint32_t b0, b1;
                ldsm_x2(b0, b1, hb + kt * 32);
                mma16816(a1[kt & 3], wreg1[kt], b0, b1);
                if (kt >= 16)
                    mma16816((kt & 1) ? a0o : a0e, wreg0[kt - 16], b0, b1);
            }
            int col = nt * 8 + 2 * ctid;
            int row = wid * 16 + gid;
            sG1[row * 17 + col]           = (a1[0][0] + a1[1][0]) + (a1[2][0] + a1[3][0]);
            sG1[row * 17 + col + 1]       = (a1[0][1] + a1[1][1]) + (a1[2][1] + a1[3][1]);
            sG1[(row + 8) * 17 + col]     = (a1[0][2] + a1[1][2]) + (a1[2][2] + a1[3][2]);
            sG1[(row + 8) * 17 + col + 1] = (a1[0][3] + a1[1][3]) + (a1[2][3] + a1[3][3]);
            sG0[row * 17 + col]           = a0e[0] + a0o[0];
            sG0[row * 17 + col + 1]       = a0e[1] + a0o[1];
            sG0[(row + 8) * 17 + col]     = a0e[2] + a0o[2];
            sG0[(row + 8) * 17 + col + 1] = a0e[3] + a0o[3];
        }
        __syncthreads();

        const int j0 = 2 * jj, j1 = j0 + 1;

        // ---- cell0 + h0 publish ----
        if (do0) {
            float gi0 = xgA.x + sG0[(0  + j0) * 17 + m_act];
            float gi1 = xgA.y + sG0[(0  + j1) * 17 + m_act];
            float gf0 = xgA.z + sG0[(32 + j0) * 17 + m_act];
            float gf1 = xgA.w + sG0[(32 + j1) * 17 + m_act];
            float gg0 = xgB.x + sG0[(64 + j0) * 17 + m_act];
            float gg1 = xgB.y + sG0[(64 + j1) * 17 + m_act];
            float go0 = xgB.z + sG0[(96 + j0) * 17 + m_act];
            float go1 = xgB.w + sG0[(96 + j1) * 17 + m_act];
            c00 = sigm(gf0) * c00 + sigm(gi0) * tanhap(gg0);
            float h0 = sigm(go0) * tanhap(c00);
            c01 = sigm(gf1) * c01 + sigm(gi1) * tanhap(gg1);
            float h1 = sigm(go1) * tanhap(c01);
            __half2 hp = __floats2half2_rn(h0, h1);
            unsigned hv = *(unsigned*)&hp;
            const unsigned src_ = offx + wb16;
#pragma unroll
            for (int rr = 0; rr < CSZ; rr++) {
                unsigned ra;
                asm volatile("mapa.shared::cluster.u32 %0, %1, %2;" : "=r"(ra) : "r"(src_), "r"(rr));
                asm volatile("st.shared::cluster.u32 [%0], %1;" :: "r"(ra), "r"(hv) : "memory");
            }
        }

        // ---- cell1 + h1 publish (or final output) ----
        if (do1) {
            float gi0 = sG1[(0  + j0) * 17 + m_act] + sB1[0  + j0];
            float gi1 = sG1[(0  + j1) * 17 + m_act] + sB1[0  + j1];
            float gf0 = sG1[(32 + j0) * 17 + m_act] + sB1[32 + j0];
            float gf1 = sG1[(32 + j1) * 17 + m_act] + sB1[32 + j1];
            float gg0 = sG1[(64 + j0) * 17 + m_act] + sB1[64 + j0];
            float gg1 = sG1[(64 + j1) * 17 + m_act] + sB1[64 + j1];
            float go0 = sG1[(96 + j0) * 17 + m_act] + sB1[96 + j0];
            float go1 = sG1[(96 + j1) * 17 + m_act] + sB1[96 + j1];
            c10 = sigm(gf0) * c10 + sigm(gi0) * tanhap(gg0);
            float h0 = sigm(go0) * tanhap(c10);
            c11 = sigm(gf1) * c11 + sigm(gi1) * tanhap(gg1);
            float h1 = sigm(go1) * tanhap(c11);
            if (s < T_) {
                __half2 hp = __floats2half2_rn(h0, h1);
                unsigned hv = *(unsigned*)&hp;
                const unsigned src_ = offh + wb16;
#pragma unroll
                for (int rr = 0; rr < CSZ; rr++) {
                    unsigned ra;
                    asm volatile("mapa.shared::cluster.u32 %0, %1, %2;" : "=r"(ra) : "r"(src_), "r"(rr));
                    asm volatile("st.shared::cluster.u32 [%0], %1;" :: "r"(ra), "r"(hv) : "memory");
                }
            } else {
                g_h2last[(bm0 + m_act) * H_ + rank * 32 + j0] = h0;
                g_h2last[(bm0 + m_act) * H_ + rank * 32 + j1] = h1;
            }
        }

        if (s < T_) {
            asm volatile("barrier.cluster.arrive.aligned;" ::: "memory");
            // xg[s+1] load in the arrive->wait slack window
            {
                int tn = (s + 1 < T_) ? s + 1 : s;
                xgA = xg4[xbase + (size_t)tn * 512];
                xgB = xg4[xbase + (size_t)tn * 512 + 1];
            }
            asm volatile("barrier.cluster.wait.aligned;" ::: "memory");
        }
    }
}

// ---------------- FC head ----------------
__global__ void head_kernel(const float* __restrict__ W1, const float* __restrict__ b1,
                            const float* __restrict__ W2, const float* __restrict__ b2,
                            float* __restrict__ out) {
    __shared__ float sLast[4][H_];
    __shared__ float sZ[4][5 * H_ + 4];
    int b0 = blockIdx.x * 4, tid = threadIdx.x;
#pragma unroll
    for (int i = 0; i < 4; i++) sLast[i][tid] = g_h2last[(b0 + i) * H_ + tid];
    __syncthreads();
#pragma unroll
    for (int q = 0; q < 5; q++) {
        int j = q * 256 + tid;
        const float* wr = W1 + (size_t)j * H_;
        float a0 = 0.f, a1 = 0.f, a2 = 0.f, a3 = 0.f;
#pragma unroll 8
        for (int k = 0; k < H_; k += 4) {
            float4 w = *(const float4*)&wr[k];
            a0 += w.x * sLast[0][k] + w.y * sLast[0][k+1] + w.z * sLast[0][k+2] + w.w * sLast[0][k+3];
            a1 += w.x * sLast[1][k] + w.y * sLast[1][k+1] + w.z * sLast[1][k+2] + w.w * sLast[1][k+3];
            a2 += w.x * sLast[2][k] + w.y * sLast[2][k+1] + w.z * sLast[2][k+2] + w.w * sLast[2][k+3];
            a3 += w.x * sLast[3][k] + w.y * sLast[3][k+1] + w.z * sLast[3][k+2] + w.w * sLast[3][k+3];
        }
        float bb = b1[j];
        sZ[0][j] = a0 + bb; sZ[1][j] = a1 + bb; sZ[2][j] = a2 + bb; sZ[3][j] = a3 + bb;
    }
    __syncthreads();
    int w = tid >> 5, l = tid & 31;
#pragma unroll
    for (int pp = 0; pp < 2; pp++) {
        int p = w + pp * 8;
        int b = p >> 2, o = p & 3;
        float acc = 0.f;
        for (int i = l; i < 1280; i += 32) acc += sZ[b][i] * W2[o * 1280 + i];
#pragma unroll
        for (int s = 16; s; s >>= 1) acc += __shfl_xor_sync(0xffffffffu, acc, s);
        if (l == 0) out[(b0 + b) * 4 + o] = acc + b2[o];
    }
}

// ---------------- launch ----------------
extern "C" void kernel_launch(void* const* d_in, const int* in_sizes, int n_in,
                              void* d_out, int out_size) {
    const float* x    = (const float*)d_in[0];
    const float* Wih0 = (const float*)d_in[1];
    const float* Whh0 = (const float*)d_in[2];
    const float* bih0 = (const float*)d_in[3];
    const float* bhh0 = (const float*)d_in[4];
    const float* Wih1 = (const float*)d_in[5];
    const float* Whh1 = (const float*)d_in[6];
    const float* bih1 = (const float*)d_in[7];
    const float* bhh1 = (const float*)d_in[8];
    const float* W1   = (const float*)d_in[9];
    const float* b1   = (const float*)d_in[10];
    const float* W2   = (const float*)d_in[11];
    const float* b2   = (const float*)d_in[12];

    constexpr int SMG = NLOC * 144 + MR * 144 + (NLOC * 17 + NLOC) * 4;   // 29952
    constexpr int SMF = 184320;

    cudaFuncSetAttribute(xg_gemm64, cudaFuncAttributeMaxDynamicSharedMemorySize, SMG);
    cudaFuncSetAttribute(lstm_fused, cudaFuncAttributeMaxDynamicSharedMemorySize, SMF);

    prep_kernel<<<2048, 64>>>(Wih0, Whh0, bih0, bhh0, Wih1, Whh1, bih1, bhh1);     // launch 0
    xg_gemm64<<<dim3(128, T_ / TCH), 256, SMG>>>(x);                               // launch 1
    probe_kernel<<<1, 32>>>();                                                     // launch 2
    lstm_fused<<<128, 256, SMF>>>();                                               // launch 3 <- ncu capture slot
    head_kernel<<<64, 256>>>(W1, b1, W2, b2, (float*)d_out);                       // launch 4
}